// round 1
// baseline (speedup 1.0000x reference)
#include <cuda_runtime.h>
#include <math.h>

#define Hd 512
#define Wd 512
#define Bn 16
#define NPIX (Bn * Hd * Wd)   // 4194304 per tensor

// Global sum-of-squares accumulator (no cudaMalloc allowed)
__device__ double g_ssq;

__global__ void zero_acc_kernel() { g_ssq = 0.0; }

#define TILE 32
#define TY 8
#define HALO 3
#define SW (TILE + 2 * HALO)   // 38
#define SP 40                  // smem pitch (pad to avoid bank conflicts)

__global__ __launch_bounds__(256) void pass1_kernel(
    const float* __restrict__ x,
    const float* __restrict__ kern,
    float* __restrict__ avg_out,
    float* __restrict__ diff_out)
{
    __shared__ float tile[SW][SP];
    __shared__ float kw[49];
    __shared__ float wsum[TILE / 4];  // >= number of warps (8)

    const int b  = blockIdx.z;
    const int x0 = blockIdx.x * TILE;
    const int y0 = blockIdx.y * TILE;
    const float* xb = x + (size_t)b * Hd * Wd;

    const int tid = threadIdx.y * 32 + threadIdx.x;
    if (tid < 49) kw[tid] = kern[tid];

    // Cooperative load of 38x38 input tile with zero padding at borders
    for (int i = tid; i < SW * SW; i += 256) {
        int ly = i / SW, lx = i % SW;
        int gy = y0 + ly - HALO;
        int gx = x0 + lx - HALO;
        float v = 0.0f;
        if ((unsigned)gy < (unsigned)Hd && (unsigned)gx < (unsigned)Wd)
            v = xb[gy * Wd + gx];
        tile[ly][lx] = v;
    }
    __syncthreads();

    const int lx = threadIdx.x;
    float ssq = 0.0f;

    #pragma unroll
    for (int r = 0; r < TILE / TY; r++) {
        const int ly = threadIdx.y + r * TY;
        const float c = tile[ly + HALO][lx + HALO];
        float sum = 0.0f;
        float diff = 0.0f;
        #pragma unroll
        for (int dy = 0; dy < 7; dy++) {
            #pragma unroll
            for (int dx = 0; dx < 7; dx++) {
                const float v = tile[ly + dy][lx + dx];
                sum += v;
                diff = fmaf(kw[dy * 7 + dx], fmaxf(v - c, 0.0f), diff);
            }
        }
        const float avg = __expf(-sum * (1.0f / 49.0f));
        const int gy = y0 + ly;
        const int gx = x0 + lx;
        const size_t idx = (size_t)b * Hd * Wd + (size_t)gy * Wd + gx;
        avg_out[idx]  = avg;
        diff_out[idx] = diff;
        const float s = 0.1f * avg + 0.9f * diff;
        ssq = fmaf(s, s, ssq);
    }

    // Block reduction of ssq -> one double atomic per block
    #pragma unroll
    for (int o = 16; o > 0; o >>= 1)
        ssq += __shfl_xor_sync(0xffffffffu, ssq, o);
    if (lx == 0) wsum[threadIdx.y] = ssq;
    __syncthreads();
    if (tid == 0) {
        float t = 0.0f;
        #pragma unroll
        for (int i = 0; i < TY; i++) t += wsum[i];
        atomicAdd(&g_ssq, (double)t);
    }
}

__global__ __launch_bounds__(256) void pass2_kernel(
    const float4* __restrict__ x,
    const float4* __restrict__ avg,
    const float4* __restrict__ diff,
    float4* __restrict__ mask)
{
    const float inv_norm = (float)(1.0 / sqrt(g_ssq));
    const int i = blockIdx.x * blockDim.x + threadIdx.x;  // NPIX/4 elements exactly

    const float4 xv = x[i];
    const float4 av = avg[i];
    const float4 dv = diff[i];
    float4 m;
    m.x = (xv.x > (0.1f * av.x + 0.9f * dv.x) * inv_norm) ? 1.0f : 0.0f;
    m.y = (xv.y > (0.1f * av.y + 0.9f * dv.y) * inv_norm) ? 1.0f : 0.0f;
    m.z = (xv.z > (0.1f * av.z + 0.9f * dv.z) * inv_norm) ? 1.0f : 0.0f;
    m.w = (xv.w > (0.1f * av.w + 0.9f * dv.w) * inv_norm) ? 1.0f : 0.0f;
    mask[i] = m;
}

extern "C" void kernel_launch(void* const* d_in, const int* in_sizes, int n_in,
                              void* d_out, int out_size)
{
    const float* x    = (const float*)d_in[0];  // [16,1,512,512]
    const float* kern = (const float*)d_in[1];  // [49]

    float* out   = (float*)d_out;
    float* mask  = out;             // [16,1,512,512]
    float* avg_o = out + NPIX;      // average_term
    float* dif_o = out + 2 * NPIX;  // differential_term

    zero_acc_kernel<<<1, 1>>>();

    dim3 blk(32, TY);
    dim3 grd(Wd / TILE, Hd / TILE, Bn);  // 16 x 16 x 16
    pass1_kernel<<<grd, blk>>>(x, kern, avg_o, dif_o);

    const int n4 = NPIX / 4;  // 1048576
    pass2_kernel<<<n4 / 256, 256>>>((const float4*)x, (const float4*)avg_o,
                                    (const float4*)dif_o, (float4*)mask);
}

// round 2
// speedup vs baseline: 1.1066x; 1.1066x over previous
#include <cuda_runtime.h>
#include <math.h>

#define Hd 512
#define Wd 512
#define Bn 16
#define NPIX (Bn * Hd * Wd)   // 4194304 per tensor

// Global sum-of-squares accumulator (no cudaMalloc allowed)
__device__ double g_ssq;

#define TW 32            // tile width
#define TH 128           // tile height
#define RPT 16           // rows per thread (TH / 8)
#define HALO 3
#define SROWS (TH + 2 * HALO)   // 134
#define SPITCH (TW + 2 * HALO)  // 38

// Map (dy,dx) offsets in [-3,3] to radial group index (r^2 -> 0..8), center excluded.
__device__ __forceinline__ constexpr int gidx(int dy, int dx) {
    int r2 = dy * dy + dx * dx;
    return (r2 == 1) ? 0 : (r2 == 2) ? 1 : (r2 == 4) ? 2 : (r2 == 5) ? 3 :
           (r2 == 8) ? 4 : (r2 == 9) ? 5 : (r2 == 10) ? 6 : (r2 == 13) ? 7 : 8; // 18
}

__global__ __launch_bounds__(256, 2) void pass1_kernel(
    const float* __restrict__ x,
    const float* __restrict__ kern,
    float* __restrict__ avg_out,
    float* __restrict__ diff_out)
{
    __shared__ float tile[SROWS][SPITCH];
    __shared__ float wsum[8];

    const int b  = blockIdx.z;
    const int x0 = blockIdx.x * TW;
    const int y0 = blockIdx.y * TH;
    const float* xb = x + (size_t)b * Hd * Wd;

    const int tx  = threadIdx.x;
    const int ty  = threadIdx.y;
    const int tid = ty * 32 + tx;

    // Cooperative load of (TH+6)x(TW+6) input tile with zero padding
    for (int i = tid; i < SROWS * SPITCH; i += 256) {
        const int ly = i / SPITCH, lx = i % SPITCH;
        const int gy = y0 + ly - HALO;
        const int gx = x0 + lx - HALO;
        float v = 0.0f;
        if ((unsigned)gy < (unsigned)Hd && (unsigned)gx < (unsigned)Wd)
            v = xb[gy * Wd + gx];
        tile[ly][lx] = v;
    }

    // Radial kernel weights: mex-hat is symmetric in r^2 = dy^2+dx^2.
    // Representative flat indices ((dy+3)*7 + dx+3) for r^2 in {1,2,4,5,8,9,10,13,18}.
    float kg[9];
    kg[0] = __ldg(&kern[25]);  // (0,1)
    kg[1] = __ldg(&kern[32]);  // (1,1)
    kg[2] = __ldg(&kern[26]);  // (0,2)
    kg[3] = __ldg(&kern[33]);  // (1,2)
    kg[4] = __ldg(&kern[40]);  // (2,2)
    kg[5] = __ldg(&kern[27]);  // (0,3)
    kg[6] = __ldg(&kern[34]);  // (1,3)
    kg[7] = __ldg(&kern[41]);  // (2,3)
    kg[8] = __ldg(&kern[48]);  // (3,3)
    // K = sum of all 49 weights (center weight = 0); multiplicities 4/8 by group.
    const float K = 4.0f * (kg[0] + kg[1] + kg[2] + kg[4] + kg[5] + kg[8])
                  + 8.0f * (kg[3] + kg[6] + kg[7]);

    __syncthreads();

    const int tybase = ty * RPT;   // first tile row (also first output row offset)

    // Sliding 7x7 register window + rolling row sums
    float w[7][7];
    float rs[7];
    float sum;

    #pragma unroll
    for (int j = 0; j < 6; j++) {
        #pragma unroll
        for (int dx = 0; dx < 7; dx++)
            w[j][dx] = tile[tybase + j][tx + dx];
        rs[j] = ((w[j][0] + w[j][1]) + (w[j][2] + w[j][3]))
              + ((w[j][4] + w[j][5]) + w[j][6]);
    }
    rs[6] = 0.0f;
    sum = ((rs[0] + rs[1]) + (rs[2] + rs[3])) + (rs[4] + rs[5]);

    float ssq = 0.0f;
    const size_t outbase = (size_t)b * Hd * Wd + (size_t)(y0 + tybase) * Wd + (x0 + tx);

    #pragma unroll
    for (int yy = 0; yy < RPT; yy++) {
        // Bring in new bottom row into slot s, update rolling sum
        const int s = (yy + 6) % 7;
        sum -= rs[s];
        const int trow = tybase + yy + 6;
        #pragma unroll
        for (int dx = 0; dx < 7; dx++)
            w[s][dx] = tile[trow][tx + dx];
        rs[s] = ((w[s][0] + w[s][1]) + (w[s][2] + w[s][3]))
              + ((w[s][4] + w[s][5]) + w[s][6]);
        sum += rs[s];

        const float c = w[(yy + 3) % 7][3];

        // diff = sum_taps k * max(v, c)  -  c * K      (== sum k*relu(v-c))
        float a0 = 0.0f, a1 = 0.0f, a2 = 0.0f, a3 = 0.0f;
        #pragma unroll
        for (int i = 0; i < 7; i++) {
            #pragma unroll
            for (int dx = 0; dx < 7; dx++) {
                if (i == 3 && dx == 3) continue;   // center: k == 0
                const float m = fmaxf(w[(yy + i) % 7][dx], c);
                const float kv = kg[gidx(i - 3, dx - 3)];
                const int a = (i * 7 + dx) & 3;
                if      (a == 0) a0 = fmaf(kv, m, a0);
                else if (a == 1) a1 = fmaf(kv, m, a1);
                else if (a == 2) a2 = fmaf(kv, m, a2);
                else             a3 = fmaf(kv, m, a3);
            }
        }
        const float diff = ((a0 + a1) + (a2 + a3)) - c * K;
        const float avg  = __expf(sum * (-1.0f / 49.0f));

        const size_t idx = outbase + (size_t)yy * Wd;
        avg_out[idx]  = avg;
        diff_out[idx] = diff;

        const float sv = 0.1f * avg + 0.9f * diff;
        ssq = fmaf(sv, sv, ssq);
    }

    // Block reduction -> one double atomic per block
    #pragma unroll
    for (int o = 16; o > 0; o >>= 1)
        ssq += __shfl_xor_sync(0xffffffffu, ssq, o);
    if (tx == 0) wsum[ty] = ssq;
    __syncthreads();
    if (tid == 0) {
        float t = 0.0f;
        #pragma unroll
        for (int i = 0; i < 8; i++) t += wsum[i];
        atomicAdd(&g_ssq, (double)t);
    }
}

__global__ __launch_bounds__(256) void pass2_kernel(
    const float4* __restrict__ x,
    const float4* __restrict__ avg,
    const float4* __restrict__ diff,
    float4* __restrict__ mask)
{
    const float inv_norm = (float)(1.0 / sqrt(g_ssq));
    const int i = blockIdx.x * blockDim.x + threadIdx.x;  // NPIX/4 elements exactly

    const float4 xv = x[i];
    const float4 av = avg[i];
    const float4 dv = diff[i];
    float4 m;
    m.x = (xv.x > (0.1f * av.x + 0.9f * dv.x) * inv_norm) ? 1.0f : 0.0f;
    m.y = (xv.y > (0.1f * av.y + 0.9f * dv.y) * inv_norm) ? 1.0f : 0.0f;
    m.z = (xv.z > (0.1f * av.z + 0.9f * dv.z) * inv_norm) ? 1.0f : 0.0f;
    m.w = (xv.w > (0.1f * av.w + 0.9f * dv.w) * inv_norm) ? 1.0f : 0.0f;
    mask[i] = m;
}

extern "C" void kernel_launch(void* const* d_in, const int* in_sizes, int n_in,
                              void* d_out, int out_size)
{
    const float* x    = (const float*)d_in[0];  // [16,1,512,512]
    const float* kern = (const float*)d_in[1];  // [49]

    float* out   = (float*)d_out;
    float* mask  = out;             // [16,1,512,512]
    float* avg_o = out + NPIX;      // average_term
    float* dif_o = out + 2 * NPIX;  // differential_term

    // Zero the accumulator via a memset node (cheaper than a 1-thread kernel)
    void* ssq_ptr = nullptr;
    cudaGetSymbolAddress(&ssq_ptr, g_ssq);
    cudaMemsetAsync(ssq_ptr, 0, sizeof(double));

    dim3 blk(32, 8);
    dim3 grd(Wd / TW, Hd / TH, Bn);  // 16 x 4 x 16
    pass1_kernel<<<grd, blk>>>(x, kern, avg_o, dif_o);

    const int n4 = NPIX / 4;  // 1048576
    pass2_kernel<<<n4 / 256, 256>>>((const float4*)x, (const float4*)avg_o,
                                    (const float4*)dif_o, (float4*)mask);
}

// round 3
// speedup vs baseline: 1.6286x; 1.4718x over previous
#include <cuda_runtime.h>
#include <math.h>

#define Hd 512
#define Wd 512
#define Bn 16
#define NPIX (Bn * Hd * Wd)   // 4194304 per tensor

// Global sum-of-squares accumulator (no cudaMalloc allowed)
__device__ double g_ssq;

#define TW 32            // tile width
#define TH 128           // tile height
#define RPT 16           // rows per thread (TH / 8)
#define HALO 3
#define SROWS (TH + 2 * HALO)   // 134
#define SPITCH (TW + 2 * HALO)  // 38

// Map (dy,dx) offsets in [-3,3] to radial group index (r^2 -> 0..8), center excluded.
__device__ __forceinline__ constexpr int gidx(int dy, int dx) {
    int r2 = dy * dy + dx * dx;
    return (r2 == 1) ? 0 : (r2 == 2) ? 1 : (r2 == 4) ? 2 : (r2 == 5) ? 3 :
           (r2 == 8) ? 4 : (r2 == 9) ? 5 : (r2 == 10) ? 6 : (r2 == 13) ? 7 : 8; // 18
}

__global__ __launch_bounds__(256, 2) void pass1_kernel(
    const float* __restrict__ x,
    const float* __restrict__ kern,
    float* __restrict__ avg_out,
    float* __restrict__ diff_out)
{
    __shared__ float tile[SROWS][SPITCH];
    __shared__ float wsum[8];

    const int b  = blockIdx.z;
    const int x0 = blockIdx.x * TW;
    const int y0 = blockIdx.y * TH;
    const float* xb = x + (size_t)b * Hd * Wd;

    const int tx  = threadIdx.x;
    const int ty  = threadIdx.y;
    const int tid = ty * 32 + tx;

    // Cooperative load of (TH+6)x(TW+6) input tile with zero padding
    for (int i = tid; i < SROWS * SPITCH; i += 256) {
        const int ly = i / SPITCH, lx = i % SPITCH;
        const int gy = y0 + ly - HALO;
        const int gx = x0 + lx - HALO;
        float v = 0.0f;
        if ((unsigned)gy < (unsigned)Hd && (unsigned)gx < (unsigned)Wd)
            v = xb[gy * Wd + gx];
        tile[ly][lx] = v;
    }

    // Radial kernel weights: mex-hat is symmetric in r^2 = dy^2+dx^2.
    float kg[9];
    kg[0] = __ldg(&kern[25]);  // (0,1)
    kg[1] = __ldg(&kern[32]);  // (1,1)
    kg[2] = __ldg(&kern[26]);  // (0,2)
    kg[3] = __ldg(&kern[33]);  // (1,2)
    kg[4] = __ldg(&kern[40]);  // (2,2)
    kg[5] = __ldg(&kern[27]);  // (0,3)
    kg[6] = __ldg(&kern[34]);  // (1,3)
    kg[7] = __ldg(&kern[41]);  // (2,3)
    kg[8] = __ldg(&kern[48]);  // (3,3)
    // K = sum of all 49 weights (center weight = 0); multiplicities 4/8 by group.
    const float K = 4.0f * (kg[0] + kg[1] + kg[2] + kg[4] + kg[5] + kg[8])
                  + 8.0f * (kg[3] + kg[6] + kg[7]);

    __syncthreads();

    const int tybase = ty * RPT;

    // Sliding 7x7 register window + rolling row sums
    float w[7][7];
    float rs[7];
    float sum;

    #pragma unroll
    for (int j = 0; j < 6; j++) {
        #pragma unroll
        for (int dx = 0; dx < 7; dx++)
            w[j][dx] = tile[tybase + j][tx + dx];
        rs[j] = ((w[j][0] + w[j][1]) + (w[j][2] + w[j][3]))
              + ((w[j][4] + w[j][5]) + w[j][6]);
    }
    rs[6] = 0.0f;
    sum = ((rs[0] + rs[1]) + (rs[2] + rs[3])) + (rs[4] + rs[5]);

    float ssq = 0.0f;
    const size_t outbase = (size_t)b * Hd * Wd + (size_t)(y0 + tybase) * Wd + (x0 + tx);

    #pragma unroll
    for (int yy = 0; yy < RPT; yy++) {
        const int s = (yy + 6) % 7;
        sum -= rs[s];
        const int trow = tybase + yy + 6;
        #pragma unroll
        for (int dx = 0; dx < 7; dx++)
            w[s][dx] = tile[trow][tx + dx];
        rs[s] = ((w[s][0] + w[s][1]) + (w[s][2] + w[s][3]))
              + ((w[s][4] + w[s][5]) + w[s][6]);
        sum += rs[s];

        const float c = w[(yy + 3) % 7][3];

        // diff = sum_taps k * max(v, c)  -  c * K      (== sum k*relu(v-c))
        float a0 = 0.0f, a1 = 0.0f, a2 = 0.0f, a3 = 0.0f;
        #pragma unroll
        for (int i = 0; i < 7; i++) {
            #pragma unroll
            for (int dx = 0; dx < 7; dx++) {
                if (i == 3 && dx == 3) continue;   // center: k == 0
                const float m = fmaxf(w[(yy + i) % 7][dx], c);
                const float kv = kg[gidx(i - 3, dx - 3)];
                const int a = (i * 7 + dx) & 3;
                if      (a == 0) a0 = fmaf(kv, m, a0);
                else if (a == 1) a1 = fmaf(kv, m, a1);
                else if (a == 2) a2 = fmaf(kv, m, a2);
                else             a3 = fmaf(kv, m, a3);
            }
        }
        const float diff = ((a0 + a1) + (a2 + a3)) - c * K;
        const float avg  = __expf(sum * (-1.0f / 49.0f));

        const size_t idx = outbase + (size_t)yy * Wd;
        avg_out[idx]  = avg;
        diff_out[idx] = diff;

        const float sv = 0.1f * avg + 0.9f * diff;
        ssq = fmaf(sv, sv, ssq);
    }

    // Block reduction -> one double atomic per block
    #pragma unroll
    for (int o = 16; o > 0; o >>= 1)
        ssq += __shfl_xor_sync(0xffffffffu, ssq, o);
    if (tx == 0) wsum[ty] = ssq;
    __syncthreads();
    if (tid == 0) {
        float t = 0.0f;
        #pragma unroll
        for (int i = 0; i < 8; i++) t += wsum[i];
        atomicAdd(&g_ssq, (double)t);
    }
}

// 2 float4 groups per thread for MLP; inv_norm computed ONCE per block in
// fp32 (rsqrtf) and broadcast via smem -- no per-thread FP64 sequences.
#define P2_VPT 2
__global__ __launch_bounds__(256) void pass2_kernel(
    const float4* __restrict__ x,
    const float4* __restrict__ avg,
    const float4* __restrict__ diff,
    float4* __restrict__ mask)
{
    __shared__ float s_inv;
    if (threadIdx.x == 0) s_inv = rsqrtf((float)g_ssq);
    __syncthreads();
    const float inv_norm = s_inv;

    const int base = (blockIdx.x * 256) * P2_VPT + threadIdx.x;

    float4 xv[P2_VPT], av[P2_VPT], dv[P2_VPT];
    #pragma unroll
    for (int j = 0; j < P2_VPT; j++) {
        const int i = base + j * 256;
        xv[j] = x[i];
        av[j] = avg[i];
        dv[j] = diff[i];
    }
    #pragma unroll
    for (int j = 0; j < P2_VPT; j++) {
        const int i = base + j * 256;
        float4 m;
        m.x = (xv[j].x > (0.1f * av[j].x + 0.9f * dv[j].x) * inv_norm) ? 1.0f : 0.0f;
        m.y = (xv[j].y > (0.1f * av[j].y + 0.9f * dv[j].y) * inv_norm) ? 1.0f : 0.0f;
        m.z = (xv[j].z > (0.1f * av[j].z + 0.9f * dv[j].z) * inv_norm) ? 1.0f : 0.0f;
        m.w = (xv[j].w > (0.1f * av[j].w + 0.9f * dv[j].w) * inv_norm) ? 1.0f : 0.0f;
        mask[i] = m;
    }
}

extern "C" void kernel_launch(void* const* d_in, const int* in_sizes, int n_in,
                              void* d_out, int out_size)
{
    const float* x    = (const float*)d_in[0];  // [16,1,512,512]
    const float* kern = (const float*)d_in[1];  // [49]

    float* out   = (float*)d_out;
    float* mask  = out;             // [16,1,512,512]
    float* avg_o = out + NPIX;      // average_term
    float* dif_o = out + 2 * NPIX;  // differential_term

    void* ssq_ptr = nullptr;
    cudaGetSymbolAddress(&ssq_ptr, g_ssq);
    cudaMemsetAsync(ssq_ptr, 0, sizeof(double));

    dim3 blk(32, 8);
    dim3 grd(Wd / TW, Hd / TH, Bn);  // 16 x 4 x 16
    pass1_kernel<<<grd, blk>>>(x, kern, avg_o, dif_o);

    const int n4 = NPIX / 4;  // 1048576
    pass2_kernel<<<n4 / (256 * P2_VPT), 256>>>(
        (const float4*)x, (const float4*)avg_o,
        (const float4*)dif_o, (float4*)mask);
}